// round 15
// baseline (speedup 1.0000x reference)
#include <cuda_runtime.h>
#include <cuda_bf16.h>

#define IMAGE_TOKEN_ID 31999
#define BB 4
#define LL 1024
#define DD 2048
#define NUM_VIS 576
#define NEW_LEN (LL - 1 + NUM_VIS)   // 1599
#define D4 (DD / 4)                  // 512 float4 per row
#define MERGED_ROWS (BB * NEW_LEN)   // 6396
#define MERGED_ELEMS (MERGED_ROWS * DD)
#define THREADS 512
#define ROWS_PER_CTA 16
#define ROW_CTAS ((MERGED_ROWS + ROWS_PER_CTA - 1) / ROWS_PER_CTA)  // 400

// Zero source row for the duplicate-scatter case (static -> zero-initialized).
__device__ float4 g_zero[D4];

// Evict-first store: keep the 52 MB output stream from thrashing L2 read lines.
__device__ __forceinline__ void stg_cs(float4* p, float4 v) {
    asm volatile("st.global.cs.v4.f32 [%0], {%1,%2,%3,%4};"
                 :: "l"(p), "f"(v.x), "f"(v.y), "f"(v.z), "f"(v.w) : "memory");
}

// Scan one batch row's 1024 ids: one int2 load per thread (512 threads).
__device__ __forceinline__ void scan_row(const int2* __restrict__ row_ids2,
                                         int t, int* s_slot) {
    int2 w = row_ids2[t];                  // ids[2t, 2t+1]
    int pos = -1;
    if (w.x == IMAGE_TOKEN_ID) pos = 2 * t;
    if (w.y == IMAGE_TOKEN_ID) pos = 2 * t + 1;
    if (pos >= 0) atomicMax(s_slot, pos);  // exactly one match per row
}

// Route output row (b, j) with image position p to a source pointer.
__device__ __forceinline__ const float4* route_row(
    int b, int j, int p,
    const int* __restrict__ ids,
    const float4* __restrict__ vis,
    const float4* __restrict__ embed)
{
    if (j >= p && j < p + NUM_VIS) {
        return vis + ((size_t)b * NUM_VIS + (j - p)) * D4;
    }
    if (j == 0 && p != 0) {
        // reference's duplicate-scatter: image row's dummy zero-write to slot 0
        // lands after text position 0's write (XLA in-order scatter).
        return g_zero;
    }
    int i = (j < p) ? j : (j - NUM_VIS + 1);
    return embed + (size_t)ids[b * LL + i] * D4;
}

// Single fused kernel: 13 tail blocks + 400 payload CTAs of 512 threads.
// Each payload CTA handles 16 rows (one float4/thread/row): 16 front-batched
// LDG.128 (default cached) + 16 evict-first STG.128, single wave on chip.
__global__ void __launch_bounds__(THREADS) merge_kernel(
    const int*    __restrict__ ids,    // [B, L]
    const float4* __restrict__ vis,    // [B, NUM_VIS, D/4]
    const float4* __restrict__ embed,  // [32768, D/4]
    float4*       __restrict__ out,    // [B, NEW_LEN, D/4] (+ tail)
    int tail_n, int tail_blocks)
{
    int blk = blockIdx.x;
    int t = threadIdx.x;

    if (blk < tail_blocks) {
        // position_ids tail: broadcast arange(NEW_LEN), as output dtype (fp32)
        int i = blk * THREADS + t;
        if (i < tail_n) {
            float* tail = (float*)out + (size_t)MERGED_ELEMS;
            tail[i] = (float)(i % NEW_LEN);
        }
        return;
    }
    blk -= tail_blocks;

    int row0 = blk * ROWS_PER_CTA;
    int b_first = row0 / NEW_LEN;
    int last_row = row0 + ROWS_PER_CTA - 1;
    if (last_row >= MERGED_ROWS) last_row = MERGED_ROWS - 1;
    int b_last = last_row / NEW_LEN;                     // <= b_first + 1

    // ---- find image-token positions for the (1 or 2) batch rows involved ----
    __shared__ int s_p[2];
    if (t < 2) s_p[t] = 0;
    __syncthreads();
    scan_row((const int2*)(ids + b_first * LL), t, &s_p[0]);
    if (b_last != b_first) {
        scan_row((const int2*)(ids + b_last * LL), t, &s_p[1]);
    }
    __syncthreads();
    int p0 = s_p[0];
    int p1 = s_p[1];

    // ---- route all rows, then pipelined loads / stores ----
    const float4* src[ROWS_PER_CTA];
    #pragma unroll
    for (int r = 0; r < ROWS_PER_CTA; r++) {
        int row = row0 + r;
        if (row < MERGED_ROWS) {
            int b = row / NEW_LEN;
            int j = row - b * NEW_LEN;
            int p = (b == b_first) ? p0 : p1;
            src[r] = route_row(b, j, p, ids, vis, embed);
        } else {
            src[r] = g_zero;   // harmless load target; store guarded below
        }
    }

    float4 v[ROWS_PER_CTA];
    #pragma unroll
    for (int r = 0; r < ROWS_PER_CTA; r++) {
        v[r] = src[r][t];
    }

    float4* dst = out + (size_t)row0 * D4;
    #pragma unroll
    for (int r = 0; r < ROWS_PER_CTA; r++) {
        if (row0 + r < MERGED_ROWS) {
            stg_cs(dst + r * D4 + t, v[r]);
        }
    }
}

extern "C" void kernel_launch(void* const* d_in, const int* in_sizes, int n_in,
                              void* d_out, int out_size) {
    const int*    ids   = (const int*)d_in[0];            // [B, L] int32
    const float4* vis   = (const float4*)d_in[1];         // [B, NUM_VIS, D]
    const float4* embed = (const float4*)d_in[2];         // [32768, D]

    int tail_n = out_size - MERGED_ELEMS;
    if (tail_n < 0) tail_n = 0;
    int tail_blocks = (tail_n + THREADS - 1) / THREADS;

    merge_kernel<<<ROW_CTAS + tail_blocks, THREADS>>>(
        ids, vis, embed, (float4*)d_out, tail_n, tail_blocks);
}

// round 16
// speedup vs baseline: 1.0253x; 1.0253x over previous
#include <cuda_runtime.h>
#include <cuda_bf16.h>

#define IMAGE_TOKEN_ID 31999
#define BB 4
#define LL 1024
#define DD 2048
#define NUM_VIS 576
#define NEW_LEN (LL - 1 + NUM_VIS)   // 1599
#define D4 (DD / 4)                  // 512 float4 per row
#define MERGED_ROWS (BB * NEW_LEN)   // 6396
#define MERGED_ELEMS (MERGED_ROWS * DD)
#define GROUP_ROWS 8                 // rows per inner group (R12 body)
#define GROUPS 2                     // groups per CTA
#define ROWS_PER_CTA (GROUP_ROWS * GROUPS)   // 16
#define ROW_CTAS ((MERGED_ROWS + ROWS_PER_CTA - 1) / ROWS_PER_CTA)  // 400

// Zero source row for the duplicate-scatter case (static -> zero-initialized).
__device__ float4 g_zero[D4];

// Evict-first store: keep the 52 MB output stream from thrashing L2 read lines.
__device__ __forceinline__ void stg_cs(float4* p, float4 v) {
    asm volatile("st.global.cs.v4.f32 [%0], {%1,%2,%3,%4};"
                 :: "l"(p), "f"(v.x), "f"(v.y), "f"(v.z), "f"(v.w) : "memory");
}

// Scan one batch row's 1024 ids with a single int4 load per thread.
__device__ __forceinline__ void scan_row(const int4* __restrict__ row_ids4,
                                         int t, int* s_slot) {
    int4 w = row_ids4[t];                  // ids[4t .. 4t+3]
    int pos = -1;
    if (w.x == IMAGE_TOKEN_ID) pos = 4 * t;
    if (w.y == IMAGE_TOKEN_ID) pos = 4 * t + 1;
    if (w.z == IMAGE_TOKEN_ID) pos = 4 * t + 2;
    if (w.w == IMAGE_TOKEN_ID) pos = 4 * t + 3;
    if (pos >= 0) atomicMax(s_slot, pos);  // exactly one match per row
}

// Route output row (b, j) with image position p to a source pointer.
__device__ __forceinline__ const float4* route_row(
    int b, int j, int p,
    const int* __restrict__ ids,
    const float4* __restrict__ vis,
    const float4* __restrict__ embed)
{
    if (j >= p && j < p + NUM_VIS) {
        return vis + ((size_t)b * NUM_VIS + (j - p)) * D4;
    }
    if (j == 0 && p != 0) {
        // reference's duplicate-scatter: image row's dummy zero-write to slot 0
        // lands after text position 0's write (XLA in-order scatter).
        return g_zero;
    }
    int i = (j < p) ? j : (j - NUM_VIS + 1);
    return embed + (size_t)ids[b * LL + i] * D4;
}

// Single-wave fused kernel: 13 tail blocks + 400 payload CTAs (256 threads).
// Each payload CTA: one ids scan + barrier, then TWO sequential groups of 8
// rows, each group = 16 front-batched LDG.128 + 16 evict-first STG.128
// (R12's proven body; only 8 routed pointers live at a time -> regs stay low).
__global__ void __launch_bounds__(256) merge_kernel(
    const int*    __restrict__ ids,    // [B, L]
    const float4* __restrict__ vis,    // [B, NUM_VIS, D/4]
    const float4* __restrict__ embed,  // [32768, D/4]
    float4*       __restrict__ out,    // [B, NEW_LEN, D/4] (+ tail)
    int tail_n, int tail_blocks)
{
    int blk = blockIdx.x;
    int t = threadIdx.x;

    if (blk < tail_blocks) {
        // position_ids tail: broadcast arange(NEW_LEN), as output dtype (fp32)
        int i = blk * 256 + t;
        if (i < tail_n) {
            float* tail = (float*)out + (size_t)MERGED_ELEMS;
            tail[i] = (float)(i % NEW_LEN);
        }
        return;
    }
    blk -= tail_blocks;

    int base = blk * ROWS_PER_CTA;
    int b_first = base / NEW_LEN;
    int last_row = base + ROWS_PER_CTA - 1;
    if (last_row >= MERGED_ROWS) last_row = MERGED_ROWS - 1;
    int b_last = last_row / NEW_LEN;                     // <= b_first + 1

    // ---- find image-token positions for the (1 or 2) batch rows involved ----
    __shared__ int s_p[2];
    if (t < 2) s_p[t] = 0;
    __syncthreads();
    scan_row((const int4*)(ids + b_first * LL), t, &s_p[0]);
    if (b_last != b_first) {
        scan_row((const int4*)(ids + b_last * LL), t, &s_p[1]);
    }
    __syncthreads();
    int p0 = s_p[0];
    int p1 = s_p[1];

    // ---- two sequential 8-row groups (R12 body each) ----
    #pragma unroll 1
    for (int g = 0; g < GROUPS; g++) {
        int row0 = base + g * GROUP_ROWS;

        const float4* src[GROUP_ROWS];
        #pragma unroll
        for (int r = 0; r < GROUP_ROWS; r++) {
            int row = row0 + r;
            if (row < MERGED_ROWS) {
                int b = row / NEW_LEN;
                int j = row - b * NEW_LEN;
                int p = (b == b_first) ? p0 : p1;
                src[r] = route_row(b, j, p, ids, vis, embed);
            } else {
                src[r] = g_zero;   // harmless load target; store guarded below
            }
        }

        float4 v[GROUP_ROWS][2];
        #pragma unroll
        for (int r = 0; r < GROUP_ROWS; r++) {
            v[r][0] = src[r][t];
            v[r][1] = src[r][t + 256];
        }

        float4* dst = out + (size_t)row0 * D4;
        #pragma unroll
        for (int r = 0; r < GROUP_ROWS; r++) {
            if (row0 + r < MERGED_ROWS) {
                stg_cs(dst + r * D4 + t,       v[r][0]);
                stg_cs(dst + r * D4 + t + 256, v[r][1]);
            }
        }
    }
}

extern "C" void kernel_launch(void* const* d_in, const int* in_sizes, int n_in,
                              void* d_out, int out_size) {
    const int*    ids   = (const int*)d_in[0];            // [B, L] int32
    const float4* vis   = (const float4*)d_in[1];         // [B, NUM_VIS, D]
    const float4* embed = (const float4*)d_in[2];         // [32768, D]

    int tail_n = out_size - MERGED_ELEMS;
    if (tail_n < 0) tail_n = 0;
    int tail_blocks = (tail_n + 255) / 256;

    merge_kernel<<<ROW_CTAS + tail_blocks, 256>>>(
        ids, vis, embed, (float4*)d_out, tail_n, tail_blocks);
}